// round 7
// baseline (speedup 1.0000x reference)
#include <cuda_runtime.h>
#include <stdint.h>

// GreedyGroupedRouter: SEQ=524288 tokens, 256 experts, 8 groups of 32, top-1/group.
// d_out layout (float32): rw[SEQ*256] | tw[SEQ*8] | tids[SEQ*8] | hist[256]
//
// R1 structure + 2-stage software pipeline: row n+1's 8 loads are issued
// before row n's compute, keeping 8 LDGs in flight per warp at all times.
// Targets the latency-bound profile (DRAM ~71%, issue ~71%, nothing saturated).

#define SEQ     524288
#define NE      256
#define NG      8
#define GS      32
#define TOPK    8
#define L2E     1.4426950408889634f

__global__ void zero_hist_kernel(float* hist) {
    hist[threadIdx.x] = 0.0f;
}

__global__ void __launch_bounds__(256, 6)   // allow ~42 regs for the prefetch buffer
router_kernel(const float* __restrict__ logits,
              float* __restrict__ rw,     // [SEQ, 256]
              float* __restrict__ tw,     // [SEQ, 8]
              float* __restrict__ tids,   // [SEQ, 8]
              float* __restrict__ hist)   // [256]
{
    __shared__ unsigned int shist[NE];
    for (int i = threadIdx.x; i < NE; i += blockDim.x) shist[i] = 0u;
    __syncthreads();

    const int lane   = threadIdx.x & 31;
    const int gwarp  = blockIdx.x * (blockDim.x >> 5) + (threadIdx.x >> 5);
    const int nwarps = gridDim.x * (blockDim.x >> 5);

    // ---- prologue: prefetch first row ----
    float c[NG];
    int row = gwarp;
    if (row < SEQ) {
        const float* lp = logits + (size_t)row * NE + lane;
        #pragma unroll
        for (int i = 0; i < NG; i++) c[i] = lp[GS * i];
    }

    for (; row < SEQ; row += nwarps) {
        // consume prefetched row
        float e[NG];
        #pragma unroll
        for (int i = 0; i < NG; i++) e[i] = c[i];

        // ---- prefetch next row immediately (8 LDGs in flight all iteration) ----
        const int nrow = row + nwarps;
        if (nrow < SEQ) {
            const float* np = logits + (size_t)nrow * NE + lane;
            #pragma unroll
            for (int i = 0; i < NG; i++) c[i] = np[GS * i];
        }

        // ---- softmax (no max subtraction: logits ~ N(0,1), fp32 safe) ----
        float s = 0.0f;
        #pragma unroll
        for (int i = 0; i < NG; i++) { e[i] = exp2f(e[i] * L2E); s += e[i]; }
        #pragma unroll
        for (int o = 16; o > 0; o >>= 1)
            s += __shfl_xor_sync(0xffffffffu, s, o);
        const float inv = 1.0f / s;

        // softmax weights + immediate streaming store (coalesced 128B each)
        float* rp = rw + (size_t)row * NE + lane;
        #pragma unroll
        for (int i = 0; i < NG; i++) {
            e[i] *= inv;
            rp[GS * i] = e[i];
        }

        // ---- per-group argmax; tie-break lowest index (lax.top_k match) ----
        float myw  = 0.0f;   // valid on lanes 0..7
        float myid = 0.0f;
        float sw   = 0.0f;
        #pragma unroll
        for (int g = 0; g < NG; g++) {
            unsigned u    = __float_as_uint(e[g]);
            unsigned umax = __reduce_max_sync(0xffffffffu, u);
            unsigned bal  = __ballot_sync(0xffffffffu, u == umax);
            int src       = __ffs(bal) - 1;
            float gv      = __uint_as_float(umax);
            sw += gv;
            if (lane == g) { myw = gv; myid = (float)(g * GS + src); }
            if (lane == src) atomicAdd(&shist[g * GS + src], 1u);
        }
        const float invsw = 1.0f / (sw + 1e-20f);

        if (lane < TOPK) {
            tw[(size_t)row * TOPK + lane]   = myw * invsw;
            tids[(size_t)row * TOPK + lane] = myid;
        }
    }

    __syncthreads();
    for (int i = threadIdx.x; i < NE; i += blockDim.x) {
        unsigned c2 = shist[i];
        if (c2) atomicAdd(&hist[i], (float)c2);
    }
}

extern "C" void kernel_launch(void* const* d_in, const int* in_sizes, int n_in,
                              void* d_out, int out_size) {
    const float* logits = (const float*)d_in[0];
    float* out  = (float*)d_out;
    float* rw   = out;
    float* tw   = rw   + (size_t)SEQ * NE;
    float* tids = tw   + (size_t)SEQ * TOPK;
    float* hist = tids + (size_t)SEQ * TOPK;

    zero_hist_kernel<<<1, NE>>>(hist);
    // 1184 blocks x 256 threads = 9472 warps, ~55 rows/warp grid-stride.
    router_kernel<<<1184, 256>>>(logits, rw, tw, tids, hist);
}

// round 8
// speedup vs baseline: 1.0766x; 1.0766x over previous
#include <cuda_runtime.h>
#include <stdint.h>

// GreedyGroupedRouter: SEQ=524288 tokens, 256 experts, 8 groups of 32, top-1/group.
// d_out layout (float32): rw[SEQ*256] | tw[SEQ*8] | tids[SEQ*8] | hist[256]
//
// Exact R1 champion router (182.0us ncu / 186.0us bench), with the separate
// zero_hist launch folded in: block 0 zeroes hist at start and publishes a
// device flag; blocks spin on the flag only at their flush point (after ~55
// rows of work, so the flag is long since set — the wait never spins in
// practice). The last block to flush resets the flag so graph replays are
// deterministic. Saves one graph node + launch gap.

#define SEQ     524288
#define NE      256
#define NG      8
#define GS      32
#define TOPK    8

__device__ unsigned g_hist_ready = 0;
__device__ unsigned g_done_blocks = 0;

__global__ void __launch_bounds__(256)
router_kernel(const float* __restrict__ logits,
              float* __restrict__ rw,     // [SEQ, 256]
              float* __restrict__ tw,     // [SEQ, 8]
              float* __restrict__ tids,   // [SEQ, 8]
              float* __restrict__ hist)   // [256]
{
    __shared__ unsigned int shist[NE];
    for (int i = threadIdx.x; i < NE; i += blockDim.x) shist[i] = 0u;

    // Block 0: zero the global histogram, then publish.
    if (blockIdx.x == 0) {
        hist[threadIdx.x] = 0.0f;         // blockDim.x == NE == 256
        __syncthreads();
        if (threadIdx.x == 0) {
            __threadfence();
            atomicExch(&g_hist_ready, 1u);
        }
    } else {
        __syncthreads();
    }

    const int lane   = threadIdx.x & 31;
    const int gwarp  = blockIdx.x * (blockDim.x >> 5) + (threadIdx.x >> 5);
    const int nwarps = gridDim.x * (blockDim.x >> 5);

    for (int row = gwarp; row < SEQ; row += nwarps) {
        const float* lp = logits + (size_t)row * NE;

        // Lane-strided: lane holds element (lane + 32*i); register i is this
        // lane's member of expert-group i. Each load is a coalesced 128B.
        float x[NG];
        #pragma unroll
        for (int i = 0; i < NG; i++) x[i] = lp[lane + GS * i];

        // Row max (softmax stabilization)
        float m = x[0];
        #pragma unroll
        for (int i = 1; i < NG; i++) m = fmaxf(m, x[i]);
        #pragma unroll
        for (int o = 16; o > 0; o >>= 1)
            m = fmaxf(m, __shfl_xor_sync(0xffffffffu, m, o));

        // exp + row sum
        float e[NG];
        float s = 0.0f;
        #pragma unroll
        for (int i = 0; i < NG; i++) { e[i] = __expf(x[i] - m); s += e[i]; }
        #pragma unroll
        for (int o = 16; o > 0; o >>= 1)
            s += __shfl_xor_sync(0xffffffffu, s, o);
        const float inv = 1.0f / s;

        // Softmax weights + immediate streaming store of routing_weights
        float* rp = rw + (size_t)row * NE;
        float w[NG];
        #pragma unroll
        for (int i = 0; i < NG; i++) {
            w[i] = e[i] * inv;
            rp[lane + GS * i] = w[i];
        }

        // Per-group argmax (group g = lanes' w[g]); tie-break to lowest index,
        // matching lax.top_k. Softmax values in (0,1] -> float bits monotone.
        float myw  = 0.0f;   // valid on lanes 0..7
        float myid = 0.0f;
        float sw   = 0.0f;
        #pragma unroll
        for (int g = 0; g < NG; g++) {
            unsigned u    = __float_as_uint(w[g]);
            unsigned umax = __reduce_max_sync(0xffffffffu, u);
            unsigned bal  = __ballot_sync(0xffffffffu, u == umax);
            int src       = __ffs(bal) - 1;           // lowest winning lane
            float gv      = __uint_as_float(umax);
            sw += gv;
            if (lane == g) { myw = gv; myid = (float)(g * GS + src); }
            if (lane == src) atomicAdd(&shist[g * GS + src], 1u);
        }
        const float invsw = 1.0f / (sw + 1e-20f);

        if (lane < TOPK) {
            tw[(size_t)row * TOPK + lane]   = myw * invsw;
            tids[(size_t)row * TOPK + lane] = myid;
        }
    }

    __syncthreads();

    // Flush: wait (in practice already set) for hist to be zeroed.
    if (threadIdx.x == 0) {
        while (atomicAdd(&g_hist_ready, 0u) == 0u) __nanosleep(64);
        __threadfence();
    }
    __syncthreads();

    for (int i = threadIdx.x; i < NE; i += blockDim.x) {
        unsigned c = shist[i];
        if (c) atomicAdd(&hist[i], (float)c);
    }

    __syncthreads();
    if (threadIdx.x == 0) {
        __threadfence();
        unsigned d = atomicAdd(&g_done_blocks, 1u);
        if (d == gridDim.x - 1) {           // last block resets for next replay
            atomicExch(&g_done_blocks, 0u);
            atomicExch(&g_hist_ready, 0u);
        }
    }
}

extern "C" void kernel_launch(void* const* d_in, const int* in_sizes, int n_in,
                              void* d_out, int out_size) {
    const float* logits = (const float*)d_in[0];
    float* out  = (float*)d_out;
    float* rw   = out;
    float* tw   = rw   + (size_t)SEQ * NE;
    float* tids = tw   + (size_t)SEQ * TOPK;
    float* hist = tids + (size_t)SEQ * TOPK;

    // Single kernel, single graph node. 1184 blocks x 256 threads = 9472
    // warps, ~55 rows/warp grid-stride.
    router_kernel<<<1184, 256>>>(logits, rw, tw, tids, hist);
}